// round 9
// baseline (speedup 1.0000x reference)
#include <cuda_runtime.h>
#include <math.h>

#define NSPEC 300
#define NPADI 304
#define NPADJ 320
#define NMEAS 9
#define NLAY  5
#define RROWS 32
#define TI    8
#define NT    38            // 304/8
#define SROW  321           // odd stride -> conflict-free column reads
#define TH_MAIN 512
#define TILEF (TI*NPADJ)    // 2560 floats per tile buffer
#define SMEM_BYTES ((5*RROWS*SROW + 2*TILEF)*4)   // 225,920 B

__device__ float  g_Minv[NLAY][NPADI][NPADJ];
__device__ double g_B[NLAY][NMEAS][NSPEC];
__device__ double g_G[NLAY][NMEAS][NSPEC];

// ---------------- PTX helpers ----------------
__device__ __forceinline__ unsigned long long pk2(float x, float y) {
    unsigned long long r; asm("mov.b64 %0,{%1,%2};" : "=l"(r) : "f"(x), "f"(y)); return r;
}
__device__ __forceinline__ void ffma2(unsigned long long& d, unsigned long long a, unsigned long long b) {
    asm("fma.rn.f32x2 %0, %1, %2, %0;" : "+l"(d) : "l"(a), "l"(b));
}
__device__ __forceinline__ void lds_v2u64(unsigned long long& a, unsigned long long& b, unsigned int addr) {
    asm volatile("ld.shared.v2.u64 {%0,%1},[%2];" : "=l"(a), "=l"(b) : "r"(addr));
}
__device__ __forceinline__ void cp16(unsigned int dst, const void* src) {
    asm volatile("cp.async.cg.shared.global [%0],[%1],16;" :: "r"(dst), "l"(src) : "memory");
}
__device__ __forceinline__ void cpcommit() { asm volatile("cp.async.commit_group;" ::: "memory"); }
template<int N> __device__ __forceinline__ void cpwait() { asm volatile("cp.async.wait_group %0;" :: "n"(N) : "memory"); }

// ============ precompute M^-1 via Woodbury (one block per layer) ============
__global__ void k_pre(const float* __restrict__ A,
                      const float* __restrict__ gamma_tv,
                      const float* __restrict__ alpha) {
    const int l = blockIdx.x, t = threadIdx.x, NTH = blockDim.x;
    const double g = gamma_tv[l], al = alpha[l];
    __shared__ double ct[NSPEC], invlam[NSPEC], vd[NSPEC];
    __shared__ double Ssm[81], Sinv[81];

    for (int m = t; m < NSPEC; m += NTH) {
        double c = cos(6.283185307179586476925287 * (double)m / (double)NSPEC);
        ct[m] = c;
        invlam[m] = 1.0 / (al + 2.0*g - 2.0*g*c);   // eigenvalues of T = al*I + g*DtD
    }
    __syncthreads();
    for (int d = t; d < NSPEC; d += NTH) {          // v[d] = (1/n) sum_m cos(2pi m d/n)/lam_m
        double s = 0.0; int idx = 0;
        for (int m = 0; m < NSPEC; m++) {
            s += ct[idx]*invlam[m];
            idx += d; if (idx >= NSPEC) idx -= NSPEC;
        }
        vd[d] = s / (double)NSPEC;
    }
    __syncthreads();
    // B[k][j] = sum_i A[k][i] * v[(i-j) mod n]
    for (int kj = t; kj < NMEAS*NSPEC; kj += NTH) {
        int k = kj / NSPEC, j = kj - k*NSPEC;
        double s0 = 0, s1 = 0;
        int d = (NSPEC - j) % NSPEC;
        for (int i = 0; i < NSPEC; i += 2) {
            int d1 = d + 1; if (d1 >= NSPEC) d1 -= NSPEC;
            s0 += (double)A[k*NSPEC + i]     * vd[d];
            s1 += (double)A[k*NSPEC + i + 1] * vd[d1];
            d += 2; if (d >= NSPEC) d -= NSPEC;
        }
        g_B[l][k][j] = s0 + s1;
    }
    __syncthreads();
    if (t < 81) {                                    // S = I9 + B A^T
        int k = t / 9, k2 = t - (t/9)*9;
        double s = (k == k2) ? 1.0 : 0.0;
        for (int j = 0; j < NSPEC; j++) s += g_B[l][k][j] * (double)A[k2*NSPEC + j];
        Ssm[t] = s;
    }
    __syncthreads();
    if (t == 0) {                                    // invert 9x9 (Gauss-Jordan, pivoted)
        double M[9][18];
        for (int r = 0; r < 9; r++)
            for (int c = 0; c < 9; c++) { M[r][c] = Ssm[r*9+c]; M[r][c+9] = (r==c) ? 1.0 : 0.0; }
        for (int c = 0; c < 9; c++) {
            int p = c; double best = fabs(M[c][c]);
            for (int r = c+1; r < 9; r++) { double v = fabs(M[r][c]); if (v > best) { best = v; p = r; } }
            if (p != c) for (int q = 0; q < 18; q++) { double tmp = M[c][q]; M[c][q] = M[p][q]; M[p][q] = tmp; }
            double piv = 1.0 / M[c][c];
            for (int q = 0; q < 18; q++) M[c][q] *= piv;
            for (int r = 0; r < 9; r++) if (r != c) {
                double f = M[r][c];
                for (int q = 0; q < 18; q++) M[r][q] -= f * M[c][q];
            }
        }
        for (int r = 0; r < 9; r++) for (int c = 0; c < 9; c++) Sinv[r*9+c] = M[r][c+9];
    }
    __syncthreads();
    for (int kj = t; kj < NMEAS*NSPEC; kj += NTH) {  // G = S^-1 B
        int k = kj / NSPEC, j = kj - (kj/NSPEC)*NSPEC;
        double s = 0;
        for (int k2 = 0; k2 < 9; k2++) s += Sinv[k*9+k2] * g_B[l][k2][j];
        g_G[l][k][j] = s;
    }
    __syncthreads();
    // Minv[i][j] = v[(i-j)%n] - sum_k B[k][i] G[k][j]; pads zeroed
    for (int ij = t; ij < NPADI*NPADJ; ij += NTH) {
        int i = ij / NPADJ, j = ij - i*NPADJ;
        float o = 0.f;
        if (i < NSPEC && j < NSPEC) {
            int d = i - j; if (d < 0) d += NSPEC;
            double s = vd[d];
            for (int k = 0; k < 9; k++) s -= g_B[l][k][i] * g_G[l][k][j];
            o = (float)s;
        }
        g_Minv[l][i][j] = o;
    }
}

// ============ fused 5-layer LADMM, 32 rows per CTA ============
extern __shared__ float smem[];

__global__ __launch_bounds__(TH_MAIN, 1)
void k_main(const float* __restrict__ b, const float* __restrict__ A,
            const float* __restrict__ gamma_tv, const float* __restrict__ lambda_tv,
            const float* __restrict__ alpha, float* __restrict__ out, int batch)
{
    const int t = threadIdx.x, lane = t & 31, w = t >> 5;   // w = column group 0..15
    const int row0 = blockIdx.x * RROWS;

    float* xs   = smem;
    float* res  = smem + RROWS*SROW;
    float* etas = smem + 2*RROWS*SROW;
    float* taus = smem + 3*RROWS*SROW;
    float* bAs  = smem + 4*RROWS*SROW;
    float* tile = smem + 5*RROWS*SROW;                       // 2 x 2560 floats; also init scratch
    const unsigned int tile_sa = (unsigned int)__cvta_generic_to_shared(tile);

    // ---- init: zero x/res buffers (pads must be 0 for i=300..303 reads) ----
    for (int e = t; e < 2*RROWS*SROW; e += TH_MAIN) smem[e] = 0.f;
    for (int e = t; e < NMEAS*NSPEC; e += TH_MAIN) tile[e] = A[e];          // A -> scratch
    if (t < RROWS*NMEAS) {
        int r = t / NMEAS, k = t - r*NMEAS;
        tile[2880 + t] = (row0 + r < batch) ? b[(size_t)(row0+r)*NMEAS + k] : 0.f;
    }
    __syncthreads();
    for (int e = t; e < RROWS*NSPEC; e += TH_MAIN) {         // bA = b@A (once), x=1, duals=0
        int r = e / NSPEC, j = e - r*NSPEC;
        float s = 0.f;
        #pragma unroll
        for (int k = 0; k < NMEAS; k++) s = fmaf(tile[2880 + r*NMEAS + k], tile[k*NSPEC + j], s);
        bAs[r*SROW + j] = s;
        xs [r*SROW + j] = 1.0f;
        etas[r*SROW + j] = 0.f;
        taus[r*SROW + j] = 0.f;
    }
    __syncthreads();

    float* px = xs;      // current x
    float* pr = res;     // residual, then x_new

    for (int l = 0; l < NLAY; l++) {
        const float g = gamma_tv[l], lam = lambda_tv[l], al = alpha[l];
        const float ig = 1.f/g, ial = 1.f/al, th = lam*ig;

        // E1: residual = bA + al*w - tau + g*u - eta
        for (int e = t; e < RROWS*NSPEC; e += TH_MAIN) {
            int r = e / NSPEC, j = e - r*NSPEC;
            int jm = (j == 0) ? (NSPEC-1) : (j-1);
            float xo = px[r*SROW+j], et = etas[r*SROW+j], ta = taus[r*SROW+j];
            float dv = (px[r*SROW+jm] - xo) + et*ig;
            float u  = copysignf(fmaxf(fabsf(dv) - th, 0.f), dv);
            float wv = fmaxf(xo + ta*ial, 0.f);
            pr[r*SROW+j] = bAs[r*SROW+j] + al*wv - ta + g*u - et;
        }
        __syncthreads();

        // matvec: x_new[j] = sum_i res[i] * Minv[i][j]  (FFMA2, cp.async double-buffer)
        unsigned long long acc[10];
        #pragma unroll
        for (int c = 0; c < 10; c++) acc[c] = 0ull;
        const float* gm = &g_Minv[l][0][0];
        for (int idx = t; idx < TILEF/4; idx += TH_MAIN)     // prefetch tile 0
            cp16(tile_sa + idx*16, gm + idx*4);
        cpcommit();
        const int rbase = lane*SROW;
        for (int kt = 0; kt < NT; kt++) {
            cpwait<0>();
            __syncthreads();                                  // tile kt visible
            if (kt + 1 < NT) {
                const float* src = gm + (kt+1)*TILEF;
                unsigned int dst = tile_sa + (unsigned)(((kt+1)&1)*TILEF*4);
                for (int idx = t; idx < TILEF/4; idx += TH_MAIN)
                    cp16(dst + idx*16, src + idx*4);
                cpcommit();
            }
            unsigned int tb = tile_sa + (unsigned)(((kt&1)*TILEF + w*20)*4);
            int i0 = kt*TI;
            #pragma unroll
            for (int ii = 0; ii < TI; ii++) {
                float bc = pr[rbase + i0 + ii];               // 32 banks, conflict-free
                unsigned long long bb = pk2(bc, bc);
                unsigned int ta2 = tb + (unsigned)(ii*NPADJ*4);
                #pragma unroll
                for (int c4 = 0; c4 < 5; c4++) {              // warp-uniform broadcast loads
                    unsigned long long p0, p1;
                    lds_v2u64(p0, p1, ta2 + c4*16);
                    ffma2(acc[2*c4],   p0, bb);
                    ffma2(acc[2*c4+1], p1, bb);
                }
            }
            __syncthreads();                                  // done reading buf kt
        }
        // write x_new over residual (pad cols give exact 0 -> pads stay 0)
        {
            int jb = w*20;
            #pragma unroll
            for (int c = 0; c < 10; c++) {
                float lo, hi;
                asm("mov.b64 {%0,%1},%2;" : "=f"(lo), "=f"(hi) : "l"(acc[c]));
                pr[rbase + jb + 2*c]     = lo;
                pr[rbase + jb + 2*c + 1] = hi;
            }
        }
        __syncthreads();

        // E2: eta += g*(dx_new - u); tau += al*(x_new - w)   (u,w recomputed from old state)
        for (int e = t; e < RROWS*NSPEC; e += TH_MAIN) {
            int r = e / NSPEC, j = e - r*NSPEC;
            int jm = (j == 0) ? (NSPEC-1) : (j-1);
            float xo = px[r*SROW+j], et = etas[r*SROW+j], ta = taus[r*SROW+j];
            float dv = (px[r*SROW+jm] - xo) + et*ig;
            float u  = copysignf(fmaxf(fabsf(dv) - th, 0.f), dv);
            float wv = fmaxf(xo + ta*ial, 0.f);
            float xn = pr[r*SROW+j], xnp = pr[r*SROW+jm];
            etas[r*SROW+j] = et + g*((xnp - xn) - u);
            taus[r*SROW+j] = ta + al*(xn - wv);
        }
        __syncthreads();
        float* tmp = px; px = pr; pr = tmp;                   // swap buffers
    }

    for (int e = t; e < RROWS*NSPEC; e += TH_MAIN) {
        int r = e / NSPEC, j = e - r*NSPEC;
        if (row0 + r < batch)
            out[(size_t)(row0 + r)*NSPEC + j] = px[r*SROW + j];
    }
}

extern "C" void kernel_launch(void* const* d_in, const int* in_sizes, int n_in,
                              void* d_out, int out_size) {
    const float* b         = (const float*)d_in[0];
    // d_in[1] = target: shape-only, values unused by the recurrence
    const float* A         = (const float*)d_in[2];
    const float* gamma_tv  = (const float*)d_in[3];
    const float* lambda_tv = (const float*)d_in[4];
    const float* alpha     = (const float*)d_in[5];
    float* out = (float*)d_out;
    int batch = in_sizes[0] / NMEAS;

    cudaFuncSetAttribute(k_main, cudaFuncAttributeMaxDynamicSharedMemorySize, SMEM_BYTES);
    k_pre <<<NLAY, 320>>>(A, gamma_tv, alpha);
    k_main<<<(batch + RROWS - 1)/RROWS, TH_MAIN, SMEM_BYTES>>>(b, A, gamma_tv, lambda_tv, alpha, out, batch);
    (void)n_in; (void)out_size;
}

// round 11
// speedup vs baseline: 2.6537x; 2.6537x over previous
#include <cuda_runtime.h>
#include <math.h>

#define NSPEC 300
#define NMEAS 9
#define NLAY  5
#define RROWS 32
#define SROW  321
#define R32   (RROWS*SROW)
#define KB    24
#define NTAP  49
#define WCOL  30
#define NTH   320
#define PACKN (64+2736+2736)
#define OFF_VS (4*R32)
#define OFF_B  (OFF_VS+64)
#define OFF_G  (OFF_B+2736)
#define OFF_Y9 (OFF_G+2736)
#define OFF_YS (OFF_Y9+4160)
#define SMEMF  (OFF_YS+416)
#define SMEMB  (SMEMF*4)
#define MAXB 131072

__device__ float  g_bA[(size_t)MAXB*NSPEC];
__device__ double g_B[NLAY][NMEAS][NSPEC];
__device__ double g_G[NLAY][NMEAS][NSPEC];
__device__ float  g_pack[NLAY][PACKN];   // [64 taps][9x304 B fp32][9x304 G fp32]

// ================= bA = b @ A (warp per row) =================
__global__ void k_bA(const float* __restrict__ b, const float* __restrict__ A, int batch) {
    int lane = threadIdx.x & 31;
    int warp = (blockIdx.x*blockDim.x + threadIdx.x) >> 5;
    int nw   = (gridDim.x*blockDim.x) >> 5;
    float Ar[10][NMEAS];
#pragma unroll
    for (int c = 0; c < 10; c++) {
        int j = lane + 32*c;
#pragma unroll
        for (int k = 0; k < NMEAS; k++) Ar[c][k] = (j < NSPEC) ? A[k*NSPEC + j] : 0.f;
    }
    for (int r = warp; r < batch; r += nw) {
        float bv[NMEAS];
#pragma unroll
        for (int k = 0; k < NMEAS; k++) bv[k] = b[(size_t)r*NMEAS + k];
#pragma unroll
        for (int c = 0; c < 10; c++) {
            int j = lane + 32*c;
            if (j < NSPEC) {
                float s = 0.f;
#pragma unroll
                for (int k = 0; k < NMEAS; k++) s = fmaf(bv[k], Ar[c][k], s);
                g_bA[(size_t)r*NSPEC + j] = s;
            }
        }
    }
}

// ====== Woodbury pieces (fp64) + fp32 pack, one block per layer ======
__global__ void k_pre(const float* __restrict__ A,
                      const float* __restrict__ gamma_tv,
                      const float* __restrict__ alpha) {
    const int l = blockIdx.x, t = threadIdx.x, NP = blockDim.x;
    const double g = gamma_tv[l], al = alpha[l];
    __shared__ double ct[NSPEC], invlam[NSPEC], vd[NSPEC];
    __shared__ double Ssm[81], Sinv[81];

    for (int m = t; m < NSPEC; m += NP) {
        double c = cos(6.283185307179586476925287*(double)m/(double)NSPEC);
        ct[m] = c;
        invlam[m] = 1.0/(al + 2.0*g - 2.0*g*c);
    }
    __syncthreads();
    for (int d = t; d < NSPEC; d += NP) {
        double s = 0.0; int idx = 0;
        for (int m = 0; m < NSPEC; m++) {
            s += ct[idx]*invlam[m];
            idx += d; if (idx >= NSPEC) idx -= NSPEC;
        }
        vd[d] = s/(double)NSPEC;
    }
    __syncthreads();
    for (int kj = t; kj < NMEAS*NSPEC; kj += NP) {    // B[k][j] = sum_i A[k][i] v[(i-j) mod n]
        int k = kj/NSPEC, j = kj - k*NSPEC;
        double s = 0.0;
        int d = (NSPEC - j) % NSPEC;
        for (int i = 0; i < NSPEC; i++) {
            s += (double)A[k*NSPEC + i]*vd[d];
            d++; if (d >= NSPEC) d -= NSPEC;
        }
        g_B[l][k][j] = s;
    }
    __syncthreads();
    if (t < 81) {                                     // S = I9 + B A^T
        int k = t/9, k2 = t - (t/9)*9;
        double s = (k == k2) ? 1.0 : 0.0;
        for (int j = 0; j < NSPEC; j++) s += g_B[l][k][j]*(double)A[k2*NSPEC + j];
        Ssm[t] = s;
    }
    __syncthreads();
    if (t == 0) {                                     // pivoted 9x9 GJ inverse, fp64
        double M[9][18];
        for (int r = 0; r < 9; r++)
            for (int c = 0; c < 9; c++) { M[r][c] = Ssm[r*9+c]; M[r][c+9] = (r==c) ? 1.0 : 0.0; }
        for (int c = 0; c < 9; c++) {
            int p = c; double best = fabs(M[c][c]);
            for (int r = c+1; r < 9; r++) { double v = fabs(M[r][c]); if (v > best) { best = v; p = r; } }
            if (p != c) for (int q = 0; q < 18; q++) { double tmp = M[c][q]; M[c][q] = M[p][q]; M[p][q] = tmp; }
            double piv = 1.0/M[c][c];
            for (int q = 0; q < 18; q++) M[c][q] *= piv;
            for (int r = 0; r < 9; r++) if (r != c) {
                double f = M[r][c];
                for (int q = 0; q < 18; q++) M[r][q] -= f*M[c][q];
            }
        }
        for (int r = 0; r < 9; r++) for (int c = 0; c < 9; c++) Sinv[r*9+c] = M[r][c+9];
    }
    __syncthreads();
    for (int kj = t; kj < NMEAS*NSPEC; kj += NP) {    // G = S^-1 B
        int k = kj/NSPEC, j = kj - (kj/NSPEC)*NSPEC;
        double s = 0;
        for (int k2 = 0; k2 < 9; k2++) s += Sinv[k*9+k2]*g_B[l][k2][j];
        g_G[l][k][j] = s;
    }
    __syncthreads();
    for (int e = t; e < PACKN; e += NP) {             // fp32 pack: taps | B | G
        float o = 0.f;
        if (e < 64) {
            if (e < NTAP) { int d = (e < KB) ? (KB - e) : (e - KB); o = (float)vd[d]; }
        } else if (e < 64 + 2736) {
            int q = e - 64, k = q/304, j = q - k*304;
            if (j < NSPEC) o = (float)g_B[l][k][j];
        } else {
            int q = e - 64 - 2736, k = q/304, j = q - k*304;
            if (j < NSPEC) o = (float)g_G[l][k][j];
        }
        g_pack[l][e] = o;
    }
}

// ====== fused 5-layer LADMM: banded conv + rank-9 correction ======
extern __shared__ float smem[];

__global__ __launch_bounds__(NTH, 1)
void k_main(const float* __restrict__ gamma_tv, const float* __restrict__ lambda_tv,
            const float* __restrict__ alpha, float* __restrict__ out, int batch)
{
    const int t = threadIdx.x, lane = t & 31, w = t >> 5;
    const int row0 = blockIdx.x*RROWS;

    float* xs   = smem;
    float* res  = smem + R32;
    float* etas = smem + 2*R32;
    float* taus = smem + 3*R32;

    for (int e = t; e < RROWS*NSPEC; e += NTH) {
        int r = e/NSPEC, j = e - r*NSPEC;
        xs[r*SROW+j] = 1.0f; etas[r*SROW+j] = 0.f; taus[r*SROW+j] = 0.f;
    }
    __syncthreads();

    float* px = xs;
    float* pr = res;

    for (int l = 0; l < NLAY; l++) {
        const float g = gamma_tv[l], lam = lambda_tv[l], al = alpha[l];
        const float ig = 1.f/g, ial = 1.f/al, th = lam*ig;

        for (int e = t; e < PACKN; e += NTH) smem[OFF_VS + e] = g_pack[l][e];

        // E1: residual = bA + al*w - tau + g*u - eta
        for (int e = t; e < RROWS*NSPEC; e += NTH) {
            int r = e/NSPEC, j = e - r*NSPEC;
            int jm = (j == 0) ? (NSPEC-1) : (j-1);
            float xo = px[r*SROW+j], et = etas[r*SROW+j], ta = taus[r*SROW+j];
            float dv = (px[r*SROW+jm] - xo) + et*ig;
            float u  = copysignf(fmaxf(fabsf(dv) - th, 0.f), dv);
            float wv = fmaxf(xo + ta*ial, 0.f);
            pr[r*SROW+j] = g_bA[(size_t)(row0+r)*NSPEC + j] + al*wv - ta + g*u - et;
        }
        __syncthreads();

        // matvec: lane = row, warp w owns columns [w*30, w*30+30)
        const int j0 = w*WCOL, rb = lane*SROW;
        float win[WCOL + 2*KB];
        #pragma unroll
        for (int d = 0; d < WCOL + 2*KB; d++) {
            int jj = j0 - KB + d;
            if (jj < 0) jj += NSPEC;
            if (jj >= NSPEC) jj -= NSPEC;
            win[d] = pr[rb + jj];                    // stride-321: conflict-free
        }
        float acc[WCOL];
        #pragma unroll
        for (int c = 0; c < WCOL; c++) acc[c] = 0.f;
        #pragma unroll
        for (int d = 0; d < NTAP; d++) {             // banded T^-1 (taps broadcast)
            float tv = smem[OFF_VS + d];
            #pragma unroll
            for (int c = 0; c < WCOL; c++) acc[c] = fmaf(win[c + d], tv, acc[c]);
        }
        float p9[9];
        #pragma unroll
        for (int k = 0; k < 9; k++) p9[k] = 0.f;
        #pragma unroll
        for (int k = 0; k < 9; k++) {                // partial y9 over this warp's i-range
            #pragma unroll
            for (int c2 = 0; c2 < 15; c2++) {
                float2 bv = *(const float2*)&smem[OFF_B + k*304 + j0 + 2*c2];
                p9[k] = fmaf(win[KB + 2*c2],     bv.x, p9[k]);
                p9[k] = fmaf(win[KB + 2*c2 + 1], bv.y, p9[k]);
            }
        }
        #pragma unroll
        for (int k = 0; k < 9; k++) smem[OFF_Y9 + w*416 + lane*13 + k] = p9[k];
        __syncthreads();
        if (t < RROWS*9) {                           // reduce y9 across 10 warps
            int r = t/9, k = t - (t/9)*9;
            float s = 0.f;
            #pragma unroll
            for (int ww = 0; ww < 10; ww++) s += smem[OFF_Y9 + ww*416 + r*13 + k];
            smem[OFF_YS + r*13 + k] = s;
        }
        __syncthreads();
        float yk[9];
        #pragma unroll
        for (int k = 0; k < 9; k++) yk[k] = smem[OFF_YS + lane*13 + k];
        #pragma unroll
        for (int k = 0; k < 9; k++) {                // x_new -= y9 . G
            #pragma unroll
            for (int c2 = 0; c2 < 15; c2++) {
                float2 gv = *(const float2*)&smem[OFF_G + k*304 + j0 + 2*c2];
                acc[2*c2]     = fmaf(-yk[k], gv.x, acc[2*c2]);
                acc[2*c2 + 1] = fmaf(-yk[k], gv.y, acc[2*c2 + 1]);
            }
        }
        #pragma unroll
        for (int c = 0; c < WCOL; c++) pr[rb + j0 + c] = acc[c];   // x_new over res
        __syncthreads();

        // E2: eta += g*(dx_new - u); tau += al*(x_new - w)
        for (int e = t; e < RROWS*NSPEC; e += NTH) {
            int r = e/NSPEC, j = e - r*NSPEC;
            int jm = (j == 0) ? (NSPEC-1) : (j-1);
            float xo = px[r*SROW+j], et = etas[r*SROW+j], ta = taus[r*SROW+j];
            float dv = (px[r*SROW+jm] - xo) + et*ig;
            float u  = copysignf(fmaxf(fabsf(dv) - th, 0.f), dv);
            float wv = fmaxf(xo + ta*ial, 0.f);
            float xn = pr[r*SROW+j], xnp = pr[r*SROW+jm];
            etas[r*SROW+j] = et + g*((xnp - xn) - u);
            taus[r*SROW+j] = ta + al*(xn - wv);
        }
        __syncthreads();
        float* tmp = px; px = pr; pr = tmp;
    }

    for (int e = t; e < RROWS*NSPEC; e += NTH) {
        int r = e/NSPEC, j = e - r*NSPEC;
        if (row0 + r < batch)
            out[(size_t)(row0 + r)*NSPEC + j] = px[r*SROW + j];
    }
}

extern "C" void kernel_launch(void* const* d_in, const int* in_sizes, int n_in,
                              void* d_out, int out_size) {
    const float* b         = (const float*)d_in[0];
    const float* A         = (const float*)d_in[2];
    const float* gamma_tv  = (const float*)d_in[3];
    const float* lambda_tv = (const float*)d_in[4];
    const float* alpha     = (const float*)d_in[5];
    float* out = (float*)d_out;
    int batch = in_sizes[0] / NMEAS;

    cudaFuncSetAttribute(k_main, cudaFuncAttributeMaxDynamicSharedMemorySize, SMEMB);
    k_pre<<<NLAY, NTH>>>(A, gamma_tv, alpha);
    k_bA <<<1024, 256>>>(b, A, batch);
    k_main<<<(batch + RROWS - 1)/RROWS, NTH, SMEMB>>>(gamma_tv, lambda_tv, alpha, out, batch);
    (void)n_in; (void)out_size;
}

// round 12
// speedup vs baseline: 3.3547x; 1.2642x over previous
#include <cuda_runtime.h>
#include <math.h>

#define NSPEC 300
#define NMEAS 9
#define NLAY  5
#define RROWS 32
#define SROW  321
#define R32   (RROWS*SROW)
#define KB    24
#define NTAP  49
#define WCOL  30
#define NTH   320
#define DPRE  60
#define PACKN (64+2736+2736)
#define OFF_BA (2*R32)
#define OFF_VS (3*R32)
#define OFF_B  (OFF_VS+64)
#define OFF_G  (OFF_B+2736)
#define OFF_Y9 (OFF_G+2736)
#define OFF_YS (OFF_Y9+4160)
#define SMEMF  (OFF_YS+416)
#define SMEMB  (SMEMF*4)
#define MAXB 131072

__device__ float g_bA[(size_t)MAXB*NSPEC];
__device__ float g_pack[NLAY][PACKN];   // [64 taps][9x304 B][9x304 G], fp32

// ================= bA = b @ A (warp per row) =================
__global__ void k_bA(const float* __restrict__ b, const float* __restrict__ A, int batch) {
    int lane = threadIdx.x & 31;
    int warp = (blockIdx.x*blockDim.x + threadIdx.x) >> 5;
    int nw   = (gridDim.x*blockDim.x) >> 5;
    float Ar[10][NMEAS];
#pragma unroll
    for (int c = 0; c < 10; c++) {
        int j = lane + 32*c;
#pragma unroll
        for (int k = 0; k < NMEAS; k++) Ar[c][k] = (j < NSPEC) ? A[k*NSPEC + j] : 0.f;
    }
    for (int r = warp; r < batch; r += nw) {
        float bv[NMEAS];
#pragma unroll
        for (int k = 0; k < NMEAS; k++) bv[k] = b[(size_t)r*NMEAS + k];
#pragma unroll
        for (int c = 0; c < 10; c++) {
            int j = lane + 32*c;
            if (j < NSPEC) {
                float s = 0.f;
#pragma unroll
                for (int k = 0; k < NMEAS; k++) s = fmaf(bv[k], Ar[c][k], s);
                g_bA[(size_t)r*NSPEC + j] = s;
            }
        }
    }
}

// ===== Woodbury setup, closed-form T^-1 kernel, banded B (1 block/layer) =====
__global__ void k_pre(const float* __restrict__ A,
                      const float* __restrict__ gamma_tv,
                      const float* __restrict__ alpha) {
    const int l = blockIdx.x, t = threadIdx.x;
    const double g = gamma_tv[l], al = alpha[l];
    __shared__ double vd[DPRE+4];
    __shared__ double Bsh[NMEAS][NSPEC];
    __shared__ double Ssm[81], Sinv[81];

    // v[d] = (r^d + r^(n-d)) / (g*(1/r - r)*(1 - r^n)),  s = r + 1/r = (al+2g)/g
    double s = (al + 2.0*g)/g;
    double r = (s - sqrt(s*s - 4.0))*0.5;
    double denom = g*(1.0/r - r)*(1.0 - pow(r, (double)NSPEC));
    if (t <= DPRE+2)
        vd[t] = (pow(r, (double)t) + pow(r, (double)(NSPEC - t)))/denom;
    __syncthreads();
    // B[k][j] = sum_{|d|<=DPRE} A[k][wrap(j+d)] * v[|d|]
    for (int kj = t; kj < NMEAS*NSPEC; kj += NTH) {
        int k = kj/NSPEC, j = kj - k*NSPEC;
        double acc = (double)A[k*NSPEC + j]*vd[0];
        for (int d = 1; d <= DPRE; d++) {
            int jp = j + d;  if (jp >= NSPEC) jp -= NSPEC;
            int jn = j - d;  if (jn < 0)      jn += NSPEC;
            acc += ((double)A[k*NSPEC + jp] + (double)A[k*NSPEC + jn])*vd[d];
        }
        Bsh[k][j] = acc;
    }
    __syncthreads();
    if (t < 81) {                                   // S = I9 + B A^T
        int k = t/9, k2 = t - (t/9)*9;
        double sacc = (k == k2) ? 1.0 : 0.0;
        for (int j = 0; j < NSPEC; j++) sacc += Bsh[k][j]*(double)A[k2*NSPEC + j];
        Ssm[t] = sacc;
    }
    __syncthreads();
    if (t == 0) {                                   // pivoted 9x9 GJ inverse, fp64
        double M[9][18];
        for (int r2 = 0; r2 < 9; r2++)
            for (int c = 0; c < 9; c++) { M[r2][c] = Ssm[r2*9+c]; M[r2][c+9] = (r2==c) ? 1.0 : 0.0; }
        for (int c = 0; c < 9; c++) {
            int p = c; double best = fabs(M[c][c]);
            for (int r2 = c+1; r2 < 9; r2++) { double v = fabs(M[r2][c]); if (v > best) { best = v; p = r2; } }
            if (p != c) for (int q = 0; q < 18; q++) { double tmp = M[c][q]; M[c][q] = M[p][q]; M[p][q] = tmp; }
            double piv = 1.0/M[c][c];
            for (int q = 0; q < 18; q++) M[c][q] *= piv;
            for (int r2 = 0; r2 < 9; r2++) if (r2 != c) {
                double f = M[r2][c];
                for (int q = 0; q < 18; q++) M[r2][q] -= f*M[c][q];
            }
        }
        for (int r2 = 0; r2 < 9; r2++) for (int c = 0; c < 9; c++) Sinv[r2*9+c] = M[r2][c+9];
    }
    __syncthreads();
    for (int e = t; e < PACKN; e += NTH) {          // pack: taps | B | G = S^-1 B
        float o = 0.f;
        if (e < 64) {
            if (e < NTAP) { int d = (e < KB) ? (KB - e) : (e - KB); o = (float)vd[d]; }
        } else if (e < 64 + 2736) {
            int q = e - 64, k = q/304, j = q - k*304;
            if (j < NSPEC) o = (float)Bsh[k][j];
        } else {
            int q = e - 64 - 2736, k = q/304, j = q - k*304;
            if (j < NSPEC) {
                double sacc = 0;
                for (int k2 = 0; k2 < 9; k2++) sacc += Sinv[k*9+k2]*Bsh[k2][j];
                o = (float)sacc;
            }
        }
        g_pack[l][e] = o;
    }
}

// ====== fused 5-layer LADMM: banded conv + rank-9, eta/tau in registers ======
extern __shared__ float smem[];

__global__ __launch_bounds__(NTH, 1)
void k_main(const float* __restrict__ gamma_tv, const float* __restrict__ lambda_tv,
            const float* __restrict__ alpha, float* __restrict__ out, int batch)
{
    const int t = threadIdx.x, lane = t & 31, w = t >> 5;
    const int row0 = blockIdx.x*RROWS;
    const int j0 = w*WCOL, rb = lane*SROW;
    const int jm0 = (j0 == 0) ? (NSPEC-1) : (j0-1);

    float* xs  = smem;
    float* rs  = smem + R32;
    float* bAs = smem + OFF_BA;

    for (int e = t; e < RROWS*NSPEC; e += NTH) {    // coalesced init
        int r = e/NSPEC, j = e - r*NSPEC;
        xs[r*SROW+j]  = 1.0f;
        bAs[r*SROW+j] = g_bA[(size_t)(row0+r)*NSPEC + j];
    }
    float eta[WCOL], tau[WCOL];
#pragma unroll
    for (int c = 0; c < WCOL; c++) { eta[c] = 0.f; tau[c] = 0.f; }
    __syncthreads();

    float* px = xs;
    float* pr = rs;

    for (int l = 0; l < NLAY; l++) {
        const float g = gamma_tv[l], lam = lambda_tv[l], al = alpha[l];
        const float ig = 1.f/g, ial = 1.f/al, th = lam*ig;

        for (int e = t; e < PACKN; e += NTH) smem[OFF_VS + e] = g_pack[l][e];

        // E1: residual (rolling neighbor, eta/tau in regs)
        {
            float xm = px[rb + jm0];
#pragma unroll
            for (int c = 0; c < WCOL; c++) {
                int j = j0 + c;
                float xo = px[rb + j];
                float dv = (xm - xo) + eta[c]*ig;
                float u  = copysignf(fmaxf(fabsf(dv) - th, 0.f), dv);
                float wv = fmaxf(xo + tau[c]*ial, 0.f);
                pr[rb + j] = bAs[rb + j] + al*wv - tau[c] + g*u - eta[c];
                xm = xo;
            }
        }
        __syncthreads();

        // window (crosses warp column boundaries)
        float win[WCOL + 2*KB];
#pragma unroll
        for (int d = 0; d < WCOL + 2*KB; d++) {
            int jj = j0 - KB + d;
            if (jj < 0) jj += NSPEC;
            if (jj >= NSPEC) jj -= NSPEC;
            win[d] = pr[rb + jj];
        }
        float acc[WCOL];
#pragma unroll
        for (int c = 0; c < WCOL; c++) acc[c] = 0.f;
#pragma unroll
        for (int d = 0; d < NTAP; d++) {            // banded T^-1
            float tv = smem[OFF_VS + d];
#pragma unroll
            for (int c = 0; c < WCOL; c++) acc[c] = fmaf(win[c + d], tv, acc[c]);
        }
        float p9[9];
#pragma unroll
        for (int k = 0; k < 9; k++) p9[k] = 0.f;
#pragma unroll
        for (int k = 0; k < 9; k++)                 // partial y9 = res . B^T
#pragma unroll
            for (int c2 = 0; c2 < 15; c2++) {
                float2 bv = *(const float2*)&smem[OFF_B + k*304 + j0 + 2*c2];
                p9[k] = fmaf(win[KB + 2*c2],     bv.x, p9[k]);
                p9[k] = fmaf(win[KB + 2*c2 + 1], bv.y, p9[k]);
            }
#pragma unroll
        for (int k = 0; k < 9; k++) smem[OFF_Y9 + w*416 + lane*13 + k] = p9[k];
        __syncthreads();
        if (t < RROWS*9) {
            int r = t/9, k = t - (t/9)*9;
            float s = 0.f;
#pragma unroll
            for (int ww = 0; ww < 10; ww++) s += smem[OFF_Y9 + ww*416 + r*13 + k];
            smem[OFF_YS + r*13 + k] = s;
        }
        __syncthreads();
        float yk[9];
#pragma unroll
        for (int k = 0; k < 9; k++) yk[k] = smem[OFF_YS + lane*13 + k];
#pragma unroll
        for (int k = 0; k < 9; k++)                 // x_new -= y9 . G
#pragma unroll
            for (int c2 = 0; c2 < 15; c2++) {
                float2 gv = *(const float2*)&smem[OFF_G + k*304 + j0 + 2*c2];
                acc[2*c2]     = fmaf(-yk[k], gv.x, acc[2*c2]);
                acc[2*c2 + 1] = fmaf(-yk[k], gv.y, acc[2*c2 + 1]);
            }
#pragma unroll
        for (int c = 0; c < WCOL; c++) pr[rb + j0 + c] = acc[c];
        __syncthreads();

        // E2: duals (x_new from acc regs; old x from px)
        {
            float xm  = px[rb + jm0];
            float xnp = pr[rb + jm0];
#pragma unroll
            for (int c = 0; c < WCOL; c++) {
                int j = j0 + c;
                float xo = px[rb + j];
                float dv = (xm - xo) + eta[c]*ig;
                float u  = copysignf(fmaxf(fabsf(dv) - th, 0.f), dv);
                float wv = fmaxf(xo + tau[c]*ial, 0.f);
                float xn = acc[c];
                eta[c] += g*((xnp - xn) - u);
                tau[c] += al*(xn - wv);
                xm = xo; xnp = xn;
            }
        }
        __syncthreads();
        float* tmp = px; px = pr; pr = tmp;
    }

    for (int e = t; e < RROWS*NSPEC; e += NTH) {    // coalesced store
        int r = e/NSPEC, j = e - r*NSPEC;
        if (row0 + r < batch)
            out[(size_t)(row0 + r)*NSPEC + j] = px[r*SROW + j];
    }
}

extern "C" void kernel_launch(void* const* d_in, const int* in_sizes, int n_in,
                              void* d_out, int out_size) {
    const float* b         = (const float*)d_in[0];
    const float* A         = (const float*)d_in[2];
    const float* gamma_tv  = (const float*)d_in[3];
    const float* lambda_tv = (const float*)d_in[4];
    const float* alpha     = (const float*)d_in[5];
    float* out = (float*)d_out;
    int batch = in_sizes[0] / NMEAS;

    cudaFuncSetAttribute(k_main, cudaFuncAttributeMaxDynamicSharedMemorySize, SMEMB);
    k_pre<<<NLAY, NTH>>>(A, gamma_tv, alpha);
    k_bA <<<1024, 256>>>(b, A, batch);
    k_main<<<(batch + RROWS - 1)/RROWS, NTH, SMEMB>>>(gamma_tv, lambda_tv, alpha, out, batch);
    (void)n_in; (void)out_size;
}

// round 13
// speedup vs baseline: 3.8255x; 1.1403x over previous
#include <cuda_runtime.h>
#include <math.h>

#define NSPEC 300
#define NMEAS 9
#define NLAY  5
#define RROWS 32
#define SROW  321
#define R32   (RROWS*SROW)
#define KB    16
#define NTAP  33
#define WCOL  30
#define NTH   320
#define DPRE  60
#define PACKN (64+2736+2736)
#define OFF_BA (2*R32)
#define OFF_VS (3*R32)
#define OFF_B  (OFF_VS+64)
#define OFF_G  (OFF_B+2736)
#define OFF_Y9 (OFF_G+2736)
#define OFF_YS (OFF_Y9+4160)
#define SMEMF  (OFF_YS+416)
#define SMEMB  (SMEMF*4)
#define MAXB 131072

__device__ float g_bA[(size_t)MAXB*NSPEC];
__device__ float g_pack[NLAY][PACKN];   // [64 taps][9x304 B][9x304 G], fp32

// ================= bA = b @ A (warp per row) =================
__global__ void k_bA(const float* __restrict__ b, const float* __restrict__ A, int batch) {
    int lane = threadIdx.x & 31;
    int warp = (blockIdx.x*blockDim.x + threadIdx.x) >> 5;
    int nw   = (gridDim.x*blockDim.x) >> 5;
    float Ar[10][NMEAS];
#pragma unroll
    for (int c = 0; c < 10; c++) {
        int j = lane + 32*c;
#pragma unroll
        for (int k = 0; k < NMEAS; k++) Ar[c][k] = (j < NSPEC) ? A[k*NSPEC + j] : 0.f;
    }
    for (int r = warp; r < batch; r += nw) {
        float bv[NMEAS];
#pragma unroll
        for (int k = 0; k < NMEAS; k++) bv[k] = b[(size_t)r*NMEAS + k];
#pragma unroll
        for (int c = 0; c < 10; c++) {
            int j = lane + 32*c;
            if (j < NSPEC) {
                float s = 0.f;
#pragma unroll
                for (int k = 0; k < NMEAS; k++) s = fmaf(bv[k], Ar[c][k], s);
                g_bA[(size_t)r*NSPEC + j] = s;
            }
        }
    }
}

// ===== Woodbury setup: closed-form T^-1 taps, banded B, PARALLEL 9x9 GJ =====
__global__ void k_pre(const float* __restrict__ A,
                      const float* __restrict__ gamma_tv,
                      const float* __restrict__ alpha) {
    const int l = blockIdx.x, t = threadIdx.x;
    const double g = gamma_tv[l], al = alpha[l];
    __shared__ double vd[DPRE+4];
    __shared__ double Bsh[NMEAS][NSPEC];
    __shared__ double Msm[9][19];          // augmented [S | I], padded row
    __shared__ double Sinv[81];
    __shared__ double fcol[9], shinv;
    __shared__ int    piv;

    // v[d] = (r^d + r^(n-d)) / (g*(1/r - r)*(1 - r^n)),  r + 1/r = (al+2g)/g
    double s = (al + 2.0*g)/g;
    double r = (s - sqrt(s*s - 4.0))*0.5;
    double denom = g*(1.0/r - r)*(1.0 - pow(r, (double)NSPEC));
    if (t <= DPRE+2)
        vd[t] = (pow(r, (double)t) + pow(r, (double)(NSPEC - t)))/denom;
    __syncthreads();

    // B[k][j] = sum_{|d|<=DPRE} A[k][wrap(j+d)] * v[|d|]   (2 indep fp64 chains)
    for (int kj = t; kj < NMEAS*NSPEC; kj += NTH) {
        int k = kj/NSPEC, j = kj - k*NSPEC;
        double a0 = (double)A[k*NSPEC + j]*vd[0], a1 = 0.0;
        for (int d = 1; d <= DPRE; d += 2) {
            int jp = j + d;     if (jp >= NSPEC) jp -= NSPEC;
            int jn = j - d;     if (jn < 0)      jn += NSPEC;
            a0 += ((double)A[k*NSPEC + jp] + (double)A[k*NSPEC + jn])*vd[d];
            int jp2 = j + d+1;  if (jp2 >= NSPEC) jp2 -= NSPEC;
            int jn2 = j - d-1;  if (jn2 < 0)      jn2 += NSPEC;
            a1 += ((double)A[k*NSPEC + jp2] + (double)A[k*NSPEC + jn2])*vd[d+1];
        }
        Bsh[k][j] = a0 + a1;
    }
    __syncthreads();

    // S = I9 + B A^T  into augmented Msm (2 chains)
    if (t < 81) {
        int k = t/9, k2 = t - (t/9)*9;
        double s0 = (k == k2) ? 1.0 : 0.0, s1 = 0.0;
        for (int j = 0; j < NSPEC; j += 2) {
            s0 += Bsh[k][j]  *(double)A[k2*NSPEC + j];
            s1 += Bsh[k][j+1]*(double)A[k2*NSPEC + j+1];
        }
        Msm[k][k2]   = s0 + s1;
        Msm[k][k2+9] = (k == k2) ? 1.0 : 0.0;
    }
    __syncthreads();

    // parallel pivoted Gauss-Jordan on 9x18
    for (int c = 0; c < 9; c++) {
        if (t == 0) {
            int p = c; double best = fabs(Msm[c][c]);
            for (int r2 = c+1; r2 < 9; r2++) { double v = fabs(Msm[r2][c]); if (v > best) { best = v; p = r2; } }
            piv = p;
        }
        __syncthreads();
        if (piv != c && t < 18) { double tmp = Msm[c][t]; Msm[c][t] = Msm[piv][t]; Msm[piv][t] = tmp; }
        __syncthreads();
        if (t == 0) shinv = 1.0/Msm[c][c];
        __syncthreads();
        if (t < 18) Msm[c][t] *= shinv;
        if (t < 9 && t != c) fcol[t] = Msm[t][c];
        __syncthreads();
        if (t < 162) {
            int r2 = t/18, q = t - (t/18)*18;
            if (r2 != c) Msm[r2][q] -= fcol[r2]*Msm[c][q];
        }
        __syncthreads();
    }
    if (t < 81) Sinv[t] = Msm[t/9][(t - (t/9)*9) + 9];
    __syncthreads();

    // pack fp32: taps | B | G = S^-1 B
    for (int e = t; e < PACKN; e += NTH) {
        float o = 0.f;
        if (e < 64) {
            if (e < NTAP) { int d = (e < KB) ? (KB - e) : (e - KB); o = (float)vd[d]; }
        } else if (e < 64 + 2736) {
            int q = e - 64, k = q/304, j = q - k*304;
            if (j < NSPEC) o = (float)Bsh[k][j];
        } else {
            int q = e - 64 - 2736, k = q/304, j = q - k*304;
            if (j < NSPEC) {
                double sacc = 0;
                for (int k2 = 0; k2 < 9; k2++) sacc += Sinv[k*9+k2]*Bsh[k2][j];
                o = (float)sacc;
            }
        }
        g_pack[l][e] = o;
    }
}

// ====== fused 5-layer LADMM: banded conv (KB=16) + rank-9, duals in regs ======
extern __shared__ float smem[];

__global__ __launch_bounds__(NTH, 1)
void k_main(const float* __restrict__ gamma_tv, const float* __restrict__ lambda_tv,
            const float* __restrict__ alpha, float* __restrict__ out, int batch)
{
    const int t = threadIdx.x, lane = t & 31, w = t >> 5;
    const int row0 = blockIdx.x*RROWS;
    const int j0 = w*WCOL, rb = lane*SROW;
    const int jm0 = (j0 == 0) ? (NSPEC-1) : (j0-1);

    float* xs  = smem;
    float* rs  = smem + R32;
    float* bAs = smem + OFF_BA;

    for (int e = t; e < RROWS*NSPEC; e += NTH) {
        int r = e/NSPEC, j = e - r*NSPEC;
        xs[r*SROW+j]  = 1.0f;
        bAs[r*SROW+j] = g_bA[(size_t)(row0+r)*NSPEC + j];
    }
    float eta[WCOL], tau[WCOL];
#pragma unroll
    for (int c = 0; c < WCOL; c++) { eta[c] = 0.f; tau[c] = 0.f; }
    __syncthreads();

    float* px = xs;
    float* pr = rs;

    for (int l = 0; l < NLAY; l++) {
        const float g = gamma_tv[l], lam = lambda_tv[l], al = alpha[l];
        const float ig = 1.f/g, ial = 1.f/al, th = lam*ig;

        for (int e = t; e < PACKN; e += NTH) smem[OFF_VS + e] = g_pack[l][e];

        // E1: residual (rolling neighbor, duals in regs)
        {
            float xm = px[rb + jm0];
#pragma unroll
            for (int c = 0; c < WCOL; c++) {
                int j = j0 + c;
                float xo = px[rb + j];
                float dv = (xm - xo) + eta[c]*ig;
                float u  = copysignf(fmaxf(fabsf(dv) - th, 0.f), dv);
                float wv = fmaxf(xo + tau[c]*ial, 0.f);
                pr[rb + j] = bAs[rb + j] + al*wv - tau[c] + g*u - eta[c];
                xm = xo;
            }
        }
        __syncthreads();

        float win[WCOL + 2*KB];
#pragma unroll
        for (int d = 0; d < WCOL + 2*KB; d++) {
            int jj = j0 - KB + d;
            if (jj < 0) jj += NSPEC;
            if (jj >= NSPEC) jj -= NSPEC;
            win[d] = pr[rb + jj];
        }
        float acc[WCOL];
#pragma unroll
        for (int c = 0; c < WCOL; c++) acc[c] = 0.f;
#pragma unroll
        for (int d = 0; d < NTAP; d++) {            // banded T^-1
            float tv = smem[OFF_VS + d];
#pragma unroll
            for (int c = 0; c < WCOL; c++) acc[c] = fmaf(win[c + d], tv, acc[c]);
        }
        float p9[9];
#pragma unroll
        for (int k = 0; k < 9; k++) p9[k] = 0.f;
#pragma unroll
        for (int k = 0; k < 9; k++)                 // partial y9 = res . B^T
#pragma unroll
            for (int c2 = 0; c2 < 15; c2++) {
                float2 bv = *(const float2*)&smem[OFF_B + k*304 + j0 + 2*c2];
                p9[k] = fmaf(win[KB + 2*c2],     bv.x, p9[k]);
                p9[k] = fmaf(win[KB + 2*c2 + 1], bv.y, p9[k]);
            }
#pragma unroll
        for (int k = 0; k < 9; k++) smem[OFF_Y9 + w*416 + lane*13 + k] = p9[k];
        __syncthreads();
        if (t < RROWS*9) {
            int r = t/9, k = t - (t/9)*9;
            float s = 0.f;
#pragma unroll
            for (int ww = 0; ww < 10; ww++) s += smem[OFF_Y9 + ww*416 + r*13 + k];
            smem[OFF_YS + r*13 + k] = s;
        }
        __syncthreads();
        float yk[9];
#pragma unroll
        for (int k = 0; k < 9; k++) yk[k] = smem[OFF_YS + lane*13 + k];
#pragma unroll
        for (int k = 0; k < 9; k++)                 // x_new -= y9 . G
#pragma unroll
            for (int c2 = 0; c2 < 15; c2++) {
                float2 gv = *(const float2*)&smem[OFF_G + k*304 + j0 + 2*c2];
                acc[2*c2]     = fmaf(-yk[k], gv.x, acc[2*c2]);
                acc[2*c2 + 1] = fmaf(-yk[k], gv.y, acc[2*c2 + 1]);
            }
#pragma unroll
        for (int c = 0; c < WCOL; c++) pr[rb + j0 + c] = acc[c];
        __syncthreads();

        // E2: duals (x_new from acc regs; old x from px)
        {
            float xm  = px[rb + jm0];
            float xnp = pr[rb + jm0];
#pragma unroll
            for (int c = 0; c < WCOL; c++) {
                int j = j0 + c;
                float xo = px[rb + j];
                float dv = (xm - xo) + eta[c]*ig;
                float u  = copysignf(fmaxf(fabsf(dv) - th, 0.f), dv);
                float wv = fmaxf(xo + tau[c]*ial, 0.f);
                float xn = acc[c];
                eta[c] += g*((xnp - xn) - u);
                tau[c] += al*(xn - wv);
                xm = xo; xnp = xn;
            }
        }
        __syncthreads();
        float* tmp = px; px = pr; pr = tmp;
    }

    for (int e = t; e < RROWS*NSPEC; e += NTH) {
        int r = e/NSPEC, j = e - r*NSPEC;
        if (row0 + r < batch)
            out[(size_t)(row0 + r)*NSPEC + j] = px[r*SROW + j];
    }
}

extern "C" void kernel_launch(void* const* d_in, const int* in_sizes, int n_in,
                              void* d_out, int out_size) {
    const float* b         = (const float*)d_in[0];
    const float* A         = (const float*)d_in[2];
    const float* gamma_tv  = (const float*)d_in[3];
    const float* lambda_tv = (const float*)d_in[4];
    const float* alpha     = (const float*)d_in[5];
    float* out = (float*)d_out;
    int batch = in_sizes[0] / NMEAS;

    cudaFuncSetAttribute(k_main, cudaFuncAttributeMaxDynamicSharedMemorySize, SMEMB);
    k_pre<<<NLAY, NTH>>>(A, gamma_tv, alpha);
    k_bA <<<1024, 256>>>(b, A, batch);
    k_main<<<(batch + RROWS - 1)/RROWS, NTH, SMEMB>>>(gamma_tv, lambda_tv, alpha, out, batch);
    (void)n_in; (void)out_size;
}

// round 14
// speedup vs baseline: 4.3767x; 1.1441x over previous
#include <cuda_runtime.h>
#include <math.h>

#define NSPEC 300
#define NMEAS 9
#define NLAY  5
#define RROWS 32
#define SROW  321
#define R32   (RROWS*SROW)
#define KB    16
#define NTAP  33
#define WCOL  30
#define NTH   320
#define DPRE  60
#define PACKN (64+2736+2736)
#define OFF_BA (2*R32)
#define OFF_VS (3*R32)
#define OFF_B  (OFF_VS+64)
#define OFF_G  (OFF_B+2736)
#define OFF_Y9 (OFF_G+2736)
#define OFF_YS (OFF_Y9+4160)
#define SMEMF  (OFF_YS+416)
#define SMEMB  (SMEMF*4)
#define MAXB 131072

__device__ float g_bA[(size_t)MAXB*NSPEC];
__device__ float g_pack[NLAY][PACKN];   // [64 taps][9x304 B][9x304 G], fp32

// ================= bA = b @ A (warp per row) =================
__global__ void k_bA(const float* __restrict__ b, const float* __restrict__ A, int batch) {
    int lane = threadIdx.x & 31;
    int warp = (blockIdx.x*blockDim.x + threadIdx.x) >> 5;
    int nw   = (gridDim.x*blockDim.x) >> 5;
    float Ar[10][NMEAS];
#pragma unroll
    for (int c = 0; c < 10; c++) {
        int j = lane + 32*c;
#pragma unroll
        for (int k = 0; k < NMEAS; k++) Ar[c][k] = (j < NSPEC) ? A[k*NSPEC + j] : 0.f;
    }
    for (int r = warp; r < batch; r += nw) {
        float bv[NMEAS];
#pragma unroll
        for (int k = 0; k < NMEAS; k++) bv[k] = b[(size_t)r*NMEAS + k];
#pragma unroll
        for (int c = 0; c < 10; c++) {
            int j = lane + 32*c;
            if (j < NSPEC) {
                float s = 0.f;
#pragma unroll
                for (int k = 0; k < NMEAS; k++) s = fmaf(bv[k], Ar[c][k], s);
                g_bA[(size_t)r*NSPEC + j] = s;
            }
        }
    }
}

// ===== Woodbury setup: fp32 band math, fp64 only for taps + 9x9 inverse =====
__global__ void k_pre(const float* __restrict__ A,
                      const float* __restrict__ gamma_tv,
                      const float* __restrict__ alpha) {
    const int l = blockIdx.x, t = threadIdx.x;
    const double g = gamma_tv[l], al = alpha[l];
    __shared__ float  vf[DPRE+4];
    __shared__ double vdd[NTAP];
    __shared__ float  Bsh[NMEAS][NSPEC];
    __shared__ double Msm[9][19];          // augmented [S | I]
    __shared__ float  Sinv[81];
    __shared__ double fcol[9], shinv;
    __shared__ int    piv;

    // taps: v[d] = (r^d + r^(n-d)) / (g*(1/r - r)*(1 - r^n)),  r + 1/r = (al+2g)/g
    double s = (al + 2.0*g)/g;
    double r = (s - sqrt(s*s - 4.0))*0.5;
    double denom = g*(1.0/r - r)*(1.0 - pow(r, (double)NSPEC));
    if (t <= DPRE+2) {
        double v = (pow(r, (double)t) + pow(r, (double)(NSPEC - t)))/denom;
        vf[t] = (float)v;
        if (t < NTAP) vdd[t] = v;
    }
    __syncthreads();

    // B[k][j] = sum_{|d|<=DPRE} A[k][wrap(j+d)] * v[|d|]   (fp32, 2 chains)
    for (int kj = t; kj < NMEAS*NSPEC; kj += NTH) {
        int k = kj/NSPEC, j = kj - k*NSPEC;
        float a0 = A[k*NSPEC + j]*vf[0], a1 = 0.f;
        for (int d = 1; d <= DPRE; d += 2) {
            int jp = j + d;     if (jp >= NSPEC) jp -= NSPEC;
            int jn = j - d;     if (jn < 0)      jn += NSPEC;
            a0 = fmaf(A[k*NSPEC + jp] + A[k*NSPEC + jn], vf[d], a0);
            int jp2 = j + d+1;  if (jp2 >= NSPEC) jp2 -= NSPEC;
            int jn2 = j - d-1;  if (jn2 < 0)      jn2 += NSPEC;
            a1 = fmaf(A[k*NSPEC + jp2] + A[k*NSPEC + jn2], vf[d+1], a1);
        }
        Bsh[k][j] = a0 + a1;
    }
    __syncthreads();

    // S = I9 + B A^T  (fp32 accumulate, 2 chains) -> fp64 augmented matrix
    if (t < 81) {
        int k = t/9, k2 = t - (t/9)*9;
        float s0 = 0.f, s1 = 0.f;
        for (int j = 0; j < NSPEC; j += 2) {
            s0 = fmaf(Bsh[k][j],   A[k2*NSPEC + j],   s0);
            s1 = fmaf(Bsh[k][j+1], A[k2*NSPEC + j+1], s1);
        }
        Msm[k][k2]   = (double)(s0 + s1) + ((k == k2) ? 1.0 : 0.0);
        Msm[k][k2+9] = (k == k2) ? 1.0 : 0.0;
    }
    __syncthreads();

    // parallel pivoted Gauss-Jordan on 9x18 (fp64, tiny)
    for (int c = 0; c < 9; c++) {
        if (t == 0) {
            int p = c; double best = fabs(Msm[c][c]);
            for (int r2 = c+1; r2 < 9; r2++) { double v = fabs(Msm[r2][c]); if (v > best) { best = v; p = r2; } }
            piv = p;
        }
        __syncthreads();
        if (piv != c && t < 18) { double tmp = Msm[c][t]; Msm[c][t] = Msm[piv][t]; Msm[piv][t] = tmp; }
        __syncthreads();
        if (t == 0) shinv = 1.0/Msm[c][c];
        __syncthreads();
        if (t < 18) Msm[c][t] *= shinv;
        if (t < 9 && t != c) fcol[t] = Msm[t][c];
        __syncthreads();
        if (t < 162) {
            int r2 = t/18, q = t - (t/18)*18;
            if (r2 != c) Msm[r2][q] -= fcol[r2]*Msm[c][q];
        }
        __syncthreads();
    }
    if (t < 81) Sinv[t] = (float)Msm[t/9][(t - (t/9)*9) + 9];
    __syncthreads();

    // pack fp32: taps | B | G = S^-1 B   (G in fp32, 9-term sums)
    for (int e = t; e < PACKN; e += NTH) {
        float o = 0.f;
        if (e < 64) {
            if (e < NTAP) { int d = (e < KB) ? (KB - e) : (e - KB); o = (float)vdd[d]; }
        } else if (e < 64 + 2736) {
            int q = e - 64, k = q/304, j = q - k*304;
            if (j < NSPEC) o = Bsh[k][j];
        } else {
            int q = e - 64 - 2736, k = q/304, j = q - k*304;
            if (j < NSPEC) {
                float sacc = 0.f;
#pragma unroll
                for (int k2 = 0; k2 < 9; k2++) sacc = fmaf(Sinv[k*9+k2], Bsh[k2][j], sacc);
                o = sacc;
            }
        }
        g_pack[l][e] = o;
    }
}

// ====== fused 5-layer LADMM: banded conv (KB=16) + rank-9, duals in regs ======
extern __shared__ float smem[];

__global__ __launch_bounds__(NTH, 1)
void k_main(const float* __restrict__ gamma_tv, const float* __restrict__ lambda_tv,
            const float* __restrict__ alpha, float* __restrict__ out, int batch)
{
    const int t = threadIdx.x, lane = t & 31, w = t >> 5;
    const int row0 = blockIdx.x*RROWS;
    const int j0 = w*WCOL, rb = lane*SROW;
    const int jm0 = (j0 == 0) ? (NSPEC-1) : (j0-1);

    float* xs  = smem;
    float* rs  = smem + R32;
    float* bAs = smem + OFF_BA;

    for (int e = t; e < RROWS*NSPEC; e += NTH) {
        int r = e/NSPEC, j = e - r*NSPEC;
        xs[r*SROW+j]  = 1.0f;
        bAs[r*SROW+j] = g_bA[(size_t)(row0+r)*NSPEC + j];
    }
    float eta[WCOL], tau[WCOL];
#pragma unroll
    for (int c = 0; c < WCOL; c++) { eta[c] = 0.f; tau[c] = 0.f; }
    __syncthreads();

    float* px = xs;
    float* pr = rs;

    for (int l = 0; l < NLAY; l++) {
        const float g = gamma_tv[l], lam = lambda_tv[l], al = alpha[l];
        const float ig = 1.f/g, ial = 1.f/al, th = lam*ig;

        for (int e = t; e < PACKN; e += NTH) smem[OFF_VS + e] = g_pack[l][e];

        // E1: residual (rolling neighbor, duals in regs)
        {
            float xm = px[rb + jm0];
#pragma unroll
            for (int c = 0; c < WCOL; c++) {
                int j = j0 + c;
                float xo = px[rb + j];
                float dv = (xm - xo) + eta[c]*ig;
                float u  = copysignf(fmaxf(fabsf(dv) - th, 0.f), dv);
                float wv = fmaxf(xo + tau[c]*ial, 0.f);
                pr[rb + j] = bAs[rb + j] + al*wv - tau[c] + g*u - eta[c];
                xm = xo;
            }
        }
        __syncthreads();

        float win[WCOL + 2*KB];
#pragma unroll
        for (int d = 0; d < WCOL + 2*KB; d++) {
            int jj = j0 - KB + d;
            if (jj < 0) jj += NSPEC;
            if (jj >= NSPEC) jj -= NSPEC;
            win[d] = pr[rb + jj];
        }
        float acc[WCOL];
#pragma unroll
        for (int c = 0; c < WCOL; c++) acc[c] = 0.f;
#pragma unroll
        for (int d = 0; d < NTAP; d++) {            // banded T^-1
            float tv = smem[OFF_VS + d];
#pragma unroll
            for (int c = 0; c < WCOL; c++) acc[c] = fmaf(win[c + d], tv, acc[c]);
        }
        float p9[9];
#pragma unroll
        for (int k = 0; k < 9; k++) p9[k] = 0.f;
#pragma unroll
        for (int k = 0; k < 9; k++)                 // partial y9 = res . B^T
#pragma unroll
            for (int c2 = 0; c2 < 15; c2++) {
                float2 bv = *(const float2*)&smem[OFF_B + k*304 + j0 + 2*c2];
                p9[k] = fmaf(win[KB + 2*c2],     bv.x, p9[k]);
                p9[k] = fmaf(win[KB + 2*c2 + 1], bv.y, p9[k]);
            }
#pragma unroll
        for (int k = 0; k < 9; k++) smem[OFF_Y9 + w*416 + lane*13 + k] = p9[k];
        __syncthreads();
        if (t < RROWS*9) {
            int r = t/9, k = t - (t/9)*9;
            float s = 0.f;
#pragma unroll
            for (int ww = 0; ww < 10; ww++) s += smem[OFF_Y9 + ww*416 + r*13 + k];
            smem[OFF_YS + r*13 + k] = s;
        }
        __syncthreads();
        float yk[9];
#pragma unroll
        for (int k = 0; k < 9; k++) yk[k] = smem[OFF_YS + lane*13 + k];
#pragma unroll
        for (int k = 0; k < 9; k++)                 // x_new -= y9 . G
#pragma unroll
            for (int c2 = 0; c2 < 15; c2++) {
                float2 gv = *(const float2*)&smem[OFF_G + k*304 + j0 + 2*c2];
                acc[2*c2]     = fmaf(-yk[k], gv.x, acc[2*c2]);
                acc[2*c2 + 1] = fmaf(-yk[k], gv.y, acc[2*c2 + 1]);
            }
#pragma unroll
        for (int c = 0; c < WCOL; c++) pr[rb + j0 + c] = acc[c];
        __syncthreads();

        // E2: duals (x_new from acc regs; old x from px)
        {
            float xm  = px[rb + jm0];
            float xnp = pr[rb + jm0];
#pragma unroll
            for (int c = 0; c < WCOL; c++) {
                int j = j0 + c;
                float xo = px[rb + j];
                float dv = (xm - xo) + eta[c]*ig;
                float u  = copysignf(fmaxf(fabsf(dv) - th, 0.f), dv);
                float wv = fmaxf(xo + tau[c]*ial, 0.f);
                float xn = acc[c];
                eta[c] += g*((xnp - xn) - u);
                tau[c] += al*(xn - wv);
                xm = xo; xnp = xn;
            }
        }
        __syncthreads();
        float* tmp = px; px = pr; pr = tmp;
    }

    for (int e = t; e < RROWS*NSPEC; e += NTH) {
        int r = e/NSPEC, j = e - r*NSPEC;
        if (row0 + r < batch)
            out[(size_t)(row0 + r)*NSPEC + j] = px[r*SROW + j];
    }
}

extern "C" void kernel_launch(void* const* d_in, const int* in_sizes, int n_in,
                              void* d_out, int out_size) {
    const float* b         = (const float*)d_in[0];
    const float* A         = (const float*)d_in[2];
    const float* gamma_tv  = (const float*)d_in[3];
    const float* lambda_tv = (const float*)d_in[4];
    const float* alpha     = (const float*)d_in[5];
    float* out = (float*)d_out;
    int batch = in_sizes[0] / NMEAS;

    cudaFuncSetAttribute(k_main, cudaFuncAttributeMaxDynamicSharedMemorySize, SMEMB);
    k_pre<<<NLAY, NTH>>>(A, gamma_tv, alpha);
    k_bA <<<1024, 256>>>(b, A, batch);
    k_main<<<(batch + RROWS - 1)/RROWS, NTH, SMEMB>>>(gamma_tv, lambda_tv, alpha, out, batch);
    (void)n_in; (void)out_size;
}

// round 15
// speedup vs baseline: 4.5209x; 1.0330x over previous
#include <cuda_runtime.h>
#include <math.h>

#define NSPEC 300
#define NMEAS 9
#define NLAY  5
#define RROWS 32
#define SROW  321
#define R32   (RROWS*SROW)
#define KB    12
#define NTAP  25
#define WCOL  20
#define NTH   480
#define NWARP 15
#define PRTH  320
#define DPRE  60
#define PACKN (64+2736+2736)
#define OFF_BA (2*R32)
#define OFF_VS (3*R32)
#define OFF_B  (OFF_VS+64)
#define OFF_G  (OFF_B+2736)
#define OFF_Y9 (OFF_G+2736)
#define OFF_YS (OFF_Y9+NWARP*416)
#define SMEMF  (OFF_YS+416)
#define SMEMB  (SMEMF*4)
#define MAXB 131072

__device__ float g_bA[(size_t)MAXB*NSPEC];
__device__ float g_pack[NLAY][PACKN];   // [64 taps][9x304 B][9x304 G], fp32

// ================= bA = b @ A (warp per row) =================
__global__ void k_bA(const float* __restrict__ b, const float* __restrict__ A, int batch) {
    int lane = threadIdx.x & 31;
    int warp = (blockIdx.x*blockDim.x + threadIdx.x) >> 5;
    int nw   = (gridDim.x*blockDim.x) >> 5;
    float Ar[10][NMEAS];
#pragma unroll
    for (int c = 0; c < 10; c++) {
        int j = lane + 32*c;
#pragma unroll
        for (int k = 0; k < NMEAS; k++) Ar[c][k] = (j < NSPEC) ? A[k*NSPEC + j] : 0.f;
    }
    for (int r = warp; r < batch; r += nw) {
        float bv[NMEAS];
#pragma unroll
        for (int k = 0; k < NMEAS; k++) bv[k] = b[(size_t)r*NMEAS + k];
#pragma unroll
        for (int c = 0; c < 10; c++) {
            int j = lane + 32*c;
            if (j < NSPEC) {
                float s = 0.f;
#pragma unroll
                for (int k = 0; k < NMEAS; k++) s = fmaf(bv[k], Ar[c][k], s);
                g_bA[(size_t)r*NSPEC + j] = s;
            }
        }
    }
}

// ===== Woodbury setup: recurrence taps, fp32 band B, fp64 9x9 GJ =====
__global__ void k_pre(const float* __restrict__ A,
                      const float* __restrict__ gamma_tv,
                      const float* __restrict__ alpha) {
    const int l = blockIdx.x, t = threadIdx.x;
    const double g = gamma_tv[l], al = alpha[l];
    __shared__ double vdm[DPRE+4];
    __shared__ float  vf[DPRE+4];
    __shared__ float  Bsh[NMEAS][NSPEC];
    __shared__ double Msm[9][19];
    __shared__ float  Sinv[81];
    __shared__ double fcol[9], shinv;
    __shared__ int    piv;

    if (t == 0) {   // taps via geometric recurrence: v[d]=(r^d + r^(n-d))/denom
        double s = (al + 2.0*g)/g;
        double r = (s - sqrt(s*s - 4.0))*0.5;
        double rn = pow(r, (double)NSPEC);
        double denom = g*(1.0/r - r)*(1.0 - rn);
        double rd = 1.0, ru = rn;
        for (int d = 0; d <= DPRE+2; d++) {
            double v = (rd + ru)/denom;
            vdm[d] = v; vf[d] = (float)v;
            rd *= r; ru /= r;
        }
    }
    __syncthreads();

    // B[k][j] = sum_{|d|<=DPRE} A[k][wrap(j+d)] * v[|d|]   (fp32, 2 chains)
    for (int kj = t; kj < NMEAS*NSPEC; kj += PRTH) {
        int k = kj/NSPEC, j = kj - k*NSPEC;
        float a0 = A[k*NSPEC + j]*vf[0], a1 = 0.f;
        for (int d = 1; d <= DPRE; d += 2) {
            int jp = j + d;     if (jp >= NSPEC) jp -= NSPEC;
            int jn = j - d;     if (jn < 0)      jn += NSPEC;
            a0 = fmaf(A[k*NSPEC + jp] + A[k*NSPEC + jn], vf[d], a0);
            int jp2 = j + d+1;  if (jp2 >= NSPEC) jp2 -= NSPEC;
            int jn2 = j - d-1;  if (jn2 < 0)      jn2 += NSPEC;
            a1 = fmaf(A[k*NSPEC + jp2] + A[k*NSPEC + jn2], vf[d+1], a1);
        }
        Bsh[k][j] = a0 + a1;
    }
    __syncthreads();

    // S = I9 + B A^T (fp32 accum) -> fp64 augmented
    if (t < 81) {
        int k = t/9, k2 = t - (t/9)*9;
        float s0 = 0.f, s1 = 0.f;
        for (int j = 0; j < NSPEC; j += 2) {
            s0 = fmaf(Bsh[k][j],   A[k2*NSPEC + j],   s0);
            s1 = fmaf(Bsh[k][j+1], A[k2*NSPEC + j+1], s1);
        }
        Msm[k][k2]   = (double)(s0 + s1) + ((k == k2) ? 1.0 : 0.0);
        Msm[k][k2+9] = (k == k2) ? 1.0 : 0.0;
    }
    __syncthreads();

    // parallel pivoted Gauss-Jordan 9x18 (fp64)
    for (int c = 0; c < 9; c++) {
        if (t == 0) {
            int p = c; double best = fabs(Msm[c][c]);
            for (int r2 = c+1; r2 < 9; r2++) { double v = fabs(Msm[r2][c]); if (v > best) { best = v; p = r2; } }
            piv = p;
        }
        __syncthreads();
        if (piv != c && t < 18) { double tmp = Msm[c][t]; Msm[c][t] = Msm[piv][t]; Msm[piv][t] = tmp; }
        __syncthreads();
        if (t == 0) shinv = 1.0/Msm[c][c];
        __syncthreads();
        if (t < 18) Msm[c][t] *= shinv;
        if (t < 9 && t != c) fcol[t] = Msm[t][c];
        __syncthreads();
        if (t < 162) {
            int r2 = t/18, q = t - (t/18)*18;
            if (r2 != c) Msm[r2][q] -= fcol[r2]*Msm[c][q];
        }
        __syncthreads();
    }
    if (t < 81) Sinv[t] = (float)Msm[t/9][(t - (t/9)*9) + 9];
    __syncthreads();

    // pack: taps | B | G = S^-1 B
    for (int e = t; e < PACKN; e += PRTH) {
        float o = 0.f;
        if (e < 64) {
            if (e < NTAP) { int d = (e < KB) ? (KB - e) : (e - KB); o = (float)vdm[d]; }
        } else if (e < 64 + 2736) {
            int q = e - 64, k = q/304, j = q - k*304;
            if (j < NSPEC) o = Bsh[k][j];
        } else {
            int q = e - 64 - 2736, k = q/304, j = q - k*304;
            if (j < NSPEC) {
                float sacc = 0.f;
#pragma unroll
                for (int k2 = 0; k2 < 9; k2++) sacc = fmaf(Sinv[k*9+k2], Bsh[k2][j], sacc);
                o = sacc;
            }
        }
        g_pack[l][e] = o;
    }
}

// ====== fused 5-layer LADMM: KB=12 band + rank-9 (float4), 15 warps ======
extern __shared__ float smem[];

__global__ __launch_bounds__(NTH, 1)
void k_main(const float* __restrict__ gamma_tv, const float* __restrict__ lambda_tv,
            const float* __restrict__ alpha, float* __restrict__ out, int batch)
{
    const int t = threadIdx.x, lane = t & 31, w = t >> 5;
    const int row0 = blockIdx.x*RROWS;
    const int j0 = w*WCOL, rb = lane*SROW;
    const int jm0 = (j0 == 0) ? (NSPEC-1) : (j0-1);

    float* xs  = smem;
    float* rs  = smem + R32;
    float* bAs = smem + OFF_BA;

    for (int e = t; e < RROWS*NSPEC; e += NTH) {
        int r = e/NSPEC, j = e - r*NSPEC;
        xs[r*SROW+j]  = 1.0f;
        bAs[r*SROW+j] = g_bA[(size_t)(row0+r)*NSPEC + j];
    }
    float eta[WCOL], tau[WCOL];
#pragma unroll
    for (int c = 0; c < WCOL; c++) { eta[c] = 0.f; tau[c] = 0.f; }
    __syncthreads();

    float* px = xs;
    float* pr = rs;

    for (int l = 0; l < NLAY; l++) {
        const float g = gamma_tv[l], lam = lambda_tv[l], al = alpha[l];
        const float ig = 1.f/g, ial = 1.f/al, th = lam*ig;

        for (int e = t; e < PACKN; e += NTH) smem[OFF_VS + e] = g_pack[l][e];

        // E1: residual (duals in regs, rolling neighbor)
        {
            float xm = px[rb + jm0];
#pragma unroll
            for (int c = 0; c < WCOL; c++) {
                int j = j0 + c;
                float xo = px[rb + j];
                float dv = (xm - xo) + eta[c]*ig;
                float u  = copysignf(fmaxf(fabsf(dv) - th, 0.f), dv);
                float wv = fmaxf(xo + tau[c]*ial, 0.f);
                pr[rb + j] = bAs[rb + j] + al*wv - tau[c] + g*u - eta[c];
                xm = xo;
            }
        }
        __syncthreads();

        float win[WCOL + 2*KB];
#pragma unroll
        for (int d = 0; d < WCOL + 2*KB; d++) {
            int jj = j0 - KB + d;
            if (jj < 0) jj += NSPEC;
            if (jj >= NSPEC) jj -= NSPEC;
            win[d] = pr[rb + jj];
        }
        float acc[WCOL];
#pragma unroll
        for (int c = 0; c < WCOL; c++) acc[c] = 0.f;
#pragma unroll
        for (int d = 0; d < NTAP; d++) {            // banded T^-1
            float tv = smem[OFF_VS + d];
#pragma unroll
            for (int c = 0; c < WCOL; c++) acc[c] = fmaf(win[c + d], tv, acc[c]);
        }
        float p9[9];
#pragma unroll
        for (int k = 0; k < 9; k++) p9[k] = 0.f;
#pragma unroll
        for (int k = 0; k < 9; k++)                 // y9 partial = res . B^T (float4)
#pragma unroll
            for (int c4 = 0; c4 < 5; c4++) {
                float4 bv = *(const float4*)&smem[OFF_B + k*304 + j0 + 4*c4];
                p9[k] = fmaf(win[KB + 4*c4],     bv.x, p9[k]);
                p9[k] = fmaf(win[KB + 4*c4 + 1], bv.y, p9[k]);
                p9[k] = fmaf(win[KB + 4*c4 + 2], bv.z, p9[k]);
                p9[k] = fmaf(win[KB + 4*c4 + 3], bv.w, p9[k]);
            }
#pragma unroll
        for (int k = 0; k < 9; k++) smem[OFF_Y9 + w*416 + lane*13 + k] = p9[k];
        __syncthreads();
        if (t < RROWS*9) {                          // reduce across 15 warps
            int r = t/9, k = t - (t/9)*9;
            float s = 0.f;
#pragma unroll
            for (int ww = 0; ww < NWARP; ww++) s += smem[OFF_Y9 + ww*416 + r*13 + k];
            smem[OFF_YS + r*13 + k] = s;
        }
        __syncthreads();
        float yk[9];
#pragma unroll
        for (int k = 0; k < 9; k++) yk[k] = smem[OFF_YS + lane*13 + k];
#pragma unroll
        for (int k = 0; k < 9; k++)                 // x_new -= y9 . G (float4)
#pragma unroll
            for (int c4 = 0; c4 < 5; c4++) {
                float4 gv = *(const float4*)&smem[OFF_G + k*304 + j0 + 4*c4];
                acc[4*c4]     = fmaf(-yk[k], gv.x, acc[4*c4]);
                acc[4*c4 + 1] = fmaf(-yk[k], gv.y, acc[4*c4 + 1]);
                acc[4*c4 + 2] = fmaf(-yk[k], gv.z, acc[4*c4 + 2]);
                acc[4*c4 + 3] = fmaf(-yk[k], gv.w, acc[4*c4 + 3]);
            }
#pragma unroll
        for (int c = 0; c < WCOL; c++) pr[rb + j0 + c] = acc[c];
        __syncthreads();

        // E2: duals (x_new from acc regs)
        {
            float xm  = px[rb + jm0];
            float xnp = pr[rb + jm0];
#pragma unroll
            for (int c = 0; c < WCOL; c++) {
                int j = j0 + c;
                float xo = px[rb + j];
                float dv = (xm - xo) + eta[c]*ig;
                float u  = copysignf(fmaxf(fabsf(dv) - th, 0.f), dv);
                float wv = fmaxf(xo + tau[c]*ial, 0.f);
                float xn = acc[c];
                eta[c] += g*((xnp - xn) - u);
                tau[c] += al*(xn - wv);
                xm = xo; xnp = xn;
            }
        }
        __syncthreads();
        float* tmp = px; px = pr; pr = tmp;
    }

    for (int e = t; e < RROWS*NSPEC; e += NTH) {
        int r = e/NSPEC, j = e - r*NSPEC;
        if (row0 + r < batch)
            out[(size_t)(row0 + r)*NSPEC + j] = px[r*SROW + j];
    }
}

extern "C" void kernel_launch(void* const* d_in, const int* in_sizes, int n_in,
                              void* d_out, int out_size) {
    const float* b         = (const float*)d_in[0];
    const float* A         = (const float*)d_in[2];
    const float* gamma_tv  = (const float*)d_in[3];
    const float* lambda_tv = (const float*)d_in[4];
    const float* alpha     = (const float*)d_in[5];
    float* out = (float*)d_out;
    int batch = in_sizes[0] / NMEAS;

    cudaFuncSetAttribute(k_main, cudaFuncAttributeMaxDynamicSharedMemorySize, SMEMB);
    k_pre<<<NLAY, PRTH>>>(A, gamma_tv, alpha);
    k_bA <<<1024, 256>>>(b, A, batch);
    k_main<<<(batch + RROWS - 1)/RROWS, NTH, SMEMB>>>(gamma_tv, lambda_tv, alpha, out, batch);
    (void)n_in; (void)out_size;
}